// round 16
// baseline (speedup 1.0000x reference)
#include <cuda_runtime.h>
#include <cuda_bf16.h>
#include <cstdint>

#define N_NODES 100000
#define N_EDGES 1600000
#define DIM 64
#define N_GRAPHS 128
#define N_LAYERS 5
#define BN_EPS 1e-5f
#define CAP 96   // per-node neighbor bucket capacity

#define NODES_PER_CTA 256
#define CTA_THREADS 512
// dynamic smem: sW (16 KB) + sX (64 KB)
#define SMEM_BYTES ((DIM * DIM + NODES_PER_CTA * DIM) * 4)

// Scratch (allocation-free rule: __device__ globals)
__device__ float g_h0[N_NODES * DIM];
__device__ float g_h1[N_NODES * DIM];
__device__ float g_pool[N_GRAPHS * DIM];
__device__ int   g_deg[N_NODES];              // static zero-init; re-zeroed at END of each launch
__device__ int   g_esrc_pad[N_NODES * CAP];   // bucketed adjacency

// packed f32x2 helpers (FFMA2 only reachable via PTX)
#define PACK2(dst, x)  asm volatile("mov.b64 %0, {%1, %1};" : "=l"(dst) : "f"(x))
#define PACK2P(dst, lo, hi) asm volatile("mov.b64 %0, {%1, %2};" : "=l"(dst) : "f"(lo), "f"(hi))
#define UNPACK2(lo, hi, v) asm volatile("mov.b64 {%0, %1}, %2;" : "=f"(lo), "=f"(hi) : "l"(v))
#define FMA2(acc, xx, ww) asm volatile("fma.rn.f32x2 %0, %1, %2, %0;" : "+l"(acc) : "l"(xx), "l"(ww))

// ---------------------------------------------------------------------------
// Bucketed adjacency build (deg[] zero on entry; re-zeroed by trailing kernel)
// ---------------------------------------------------------------------------
__global__ void fillb_kernel(const int* __restrict__ ei,
                             int* __restrict__ deg,
                             int* __restrict__ esrc_pad) {
    int e = blockIdx.x * blockDim.x + threadIdx.x;
    if (e < N_EDGES) {
        int d = ei[N_EDGES + e];
        int c = atomicAdd(&deg[d], 1);
        if (c < CAP) esrc_pad[d * CAP + c] = ei[e];
    }
}

__global__ void zero_deg_kernel(int* __restrict__ deg) {
    int i = blockIdx.x * blockDim.x + threadIdx.x;
    if (i < N_NODES) deg[i] = 0;
}

// ---------------------------------------------------------------------------
// Fused layer, 256 nodes/CTA, 512 threads, 80 KB dynamic smem.
// GEMM: thread (nd,ng) computes 8 nodes x 4 dims; each warp W-load serves
// 16 node-rows -> W smem wavefronts halve vs the 128-node tile.
// Register-lean body (R14 form, 64 regs): stage 4 w pairs, stream xv.
// ---------------------------------------------------------------------------
__global__ void __launch_bounds__(CTA_THREADS, 2) layer_kernel(
    const float* __restrict__ h, float* __restrict__ out,
    const int* __restrict__ deg, const int* __restrict__ esrc_pad,
    const float* __restrict__ W1, const float* __restrict__ b1,
    const float* __restrict__ gamma, const float* __restrict__ beta,
    const float* __restrict__ rmean, const float* __restrict__ rvar,
    const float* __restrict__ W2, const float* __restrict__ b2) {
    extern __shared__ float smem[];
    float (*sW)[DIM] = reinterpret_cast<float(*)[DIM]>(smem);                 // 16 KB
    float (*sX)[DIM] = reinterpret_cast<float(*)[DIM]>(smem + DIM * DIM);    // 64 KB

    int tid = threadIdx.x;
    int node0 = blockIdx.x * NODES_PER_CTA;

    // load W1 (independent of gather)
    for (int i = tid; i < DIM * DIM; i += CTA_THREADS) sW[i >> 6][i & 63] = W1[i];

    // ---- gather phase: 32 node slots x 16 dim quads, 8 batches ----
    int g32 = tid >> 4;        // node slot 0..31
    int l16 = tid & 15;        // dim quad  0..15
    for (int nb = 0; nb < 8; nb++) {
        int row = nb * 32 + g32;
        int node = node0 + row;
        float4 acc = make_float4(0.f, 0.f, 0.f, 0.f);
        if (node < N_NODES) {
            acc = *reinterpret_cast<const float4*>(&h[node * DIM + l16 * 4]);
            int dn = deg[node];
            if (dn > CAP) dn = CAP;
            const int* nb_base = &esrc_pad[node * CAP];
            int j = 0;
            for (; j + 7 < dn; j += 8) {
                int s0 = nb_base[j],     s1 = nb_base[j + 1], s2 = nb_base[j + 2], s3 = nb_base[j + 3];
                int s4 = nb_base[j + 4], s5 = nb_base[j + 5], s6 = nb_base[j + 6], s7 = nb_base[j + 7];
                float4 v0 = *reinterpret_cast<const float4*>(&h[s0 * DIM + l16 * 4]);
                float4 v1 = *reinterpret_cast<const float4*>(&h[s1 * DIM + l16 * 4]);
                float4 v2 = *reinterpret_cast<const float4*>(&h[s2 * DIM + l16 * 4]);
                float4 v3 = *reinterpret_cast<const float4*>(&h[s3 * DIM + l16 * 4]);
                float4 v4 = *reinterpret_cast<const float4*>(&h[s4 * DIM + l16 * 4]);
                float4 v5 = *reinterpret_cast<const float4*>(&h[s5 * DIM + l16 * 4]);
                float4 v6 = *reinterpret_cast<const float4*>(&h[s6 * DIM + l16 * 4]);
                float4 v7 = *reinterpret_cast<const float4*>(&h[s7 * DIM + l16 * 4]);
                acc.x += ((v0.x + v1.x) + (v2.x + v3.x)) + ((v4.x + v5.x) + (v6.x + v7.x));
                acc.y += ((v0.y + v1.y) + (v2.y + v3.y)) + ((v4.y + v5.y) + (v6.y + v7.y));
                acc.z += ((v0.z + v1.z) + (v2.z + v3.z)) + ((v4.z + v5.z) + (v6.z + v7.z));
                acc.w += ((v0.w + v1.w) + (v2.w + v3.w)) + ((v4.w + v5.w) + (v6.w + v7.w));
            }
            for (; j + 3 < dn; j += 4) {
                int s0 = nb_base[j], s1 = nb_base[j + 1], s2 = nb_base[j + 2], s3 = nb_base[j + 3];
                float4 v0 = *reinterpret_cast<const float4*>(&h[s0 * DIM + l16 * 4]);
                float4 v1 = *reinterpret_cast<const float4*>(&h[s1 * DIM + l16 * 4]);
                float4 v2 = *reinterpret_cast<const float4*>(&h[s2 * DIM + l16 * 4]);
                float4 v3 = *reinterpret_cast<const float4*>(&h[s3 * DIM + l16 * 4]);
                acc.x += (v0.x + v1.x) + (v2.x + v3.x);
                acc.y += (v0.y + v1.y) + (v2.y + v3.y);
                acc.z += (v0.z + v1.z) + (v2.z + v3.z);
                acc.w += (v0.w + v1.w) + (v2.w + v3.w);
            }
            for (; j < dn; j++) {
                float4 v = *reinterpret_cast<const float4*>(&h[nb_base[j] * DIM + l16 * 4]);
                acc.x += v.x; acc.y += v.y; acc.z += v.z; acc.w += v.w;
            }
        }
        *reinterpret_cast<float4*>(&sX[row][l16 * 4]) = acc;
    }
    __syncthreads();

    int nd = tid & 15;   // dim group: dims [nd*4, nd*4+4)
    int ng = tid >> 4;   // node base: rows {ng, ng+32, ..., ng+224}
    uint32_t sw_base = (uint32_t)__cvta_generic_to_shared(sW);
    uint32_t sx_base = (uint32_t)__cvta_generic_to_shared(sX);
    uint32_t wcol = sw_base + nd * 16;           // byte offset of sW[0][nd*4]
    uint32_t xrow = sx_base + ng * (DIM * 4);    // byte offset of sX[ng][0]

    unsigned long long al[8], ah[8];

    // ---- GEMM macro body: 4 staged w pairs per k4, xv streamed per node ----
#define GEMM_BODY() \
    _Pragma("unroll 2") \
    for (int k4 = 0; k4 < DIM; k4 += 4) { \
        unsigned long long w0a, w0b, w1a, w1b, w2a, w2b, w3a, w3b; \
        asm volatile("ld.shared.v2.u64 {%0, %1}, [%2];" : "=l"(w0a), "=l"(w0b) : "r"(wcol + (k4 + 0) * (DIM * 4))); \
        asm volatile("ld.shared.v2.u64 {%0, %1}, [%2];" : "=l"(w1a), "=l"(w1b) : "r"(wcol + (k4 + 1) * (DIM * 4))); \
        asm volatile("ld.shared.v2.u64 {%0, %1}, [%2];" : "=l"(w2a), "=l"(w2b) : "r"(wcol + (k4 + 2) * (DIM * 4))); \
        asm volatile("ld.shared.v2.u64 {%0, %1}, [%2];" : "=l"(w3a), "=l"(w3b) : "r"(wcol + (k4 + 3) * (DIM * 4))); \
        _Pragma("unroll") \
        for (int i = 0; i < 8; i++) { \
            float xv0, xv1, xv2, xv3; \
            asm volatile("ld.shared.v4.f32 {%0, %1, %2, %3}, [%4];" \
                         : "=f"(xv0), "=f"(xv1), "=f"(xv2), "=f"(xv3) \
                         : "r"(xrow + i * 32 * (DIM * 4) + k4 * 4)); \
            unsigned long long xp; \
            PACK2(xp, xv0); FMA2(al[i], xp, w0a); FMA2(ah[i], xp, w0b); \
            PACK2(xp, xv1); FMA2(al[i], xp, w1a); FMA2(ah[i], xp, w1b); \
            PACK2(xp, xv2); FMA2(al[i], xp, w2a); FMA2(ah[i], xp, w2b); \
            PACK2(xp, xv3); FMA2(al[i], xp, w3a); FMA2(ah[i], xp, w3b); \
        } \
    }

    // ---- GEMM 1 ----
#pragma unroll
    for (int i = 0; i < 8; i++) { al[i] = 0; ah[i] = 0; }
    GEMM_BODY();
    __syncthreads();  // done reading sW/sX

    // BN + relu -> sX ; load W2. BN fold computed per-thread in regs.
    {
        float bnA[4], bnB[4];
#pragma unroll
        for (int j = 0; j < 4; j++) {
            int d = nd * 4 + j;
            float s = gamma[d] * rsqrtf(rvar[d] + BN_EPS);
            bnA[j] = s;
            bnB[j] = (b1[d] - rmean[d]) * s + beta[d];
        }
#pragma unroll
        for (int i = 0; i < 8; i++) {
            float v0, v1, v2, v3;
            UNPACK2(v0, v1, al[i]); UNPACK2(v2, v3, ah[i]);
            int row = ng + 32 * i;
            sX[row][nd * 4 + 0] = fmaxf(v0 * bnA[0] + bnB[0], 0.f);
            sX[row][nd * 4 + 1] = fmaxf(v1 * bnA[1] + bnB[1], 0.f);
            sX[row][nd * 4 + 2] = fmaxf(v2 * bnA[2] + bnB[2], 0.f);
            sX[row][nd * 4 + 3] = fmaxf(v3 * bnA[3] + bnB[3], 0.f);
        }
    }
    for (int i = tid; i < DIM * DIM; i += CTA_THREADS) sW[i >> 6][i & 63] = W2[i];
    __syncthreads();

    // ---- GEMM 2, acc pre-seeded with b2 ----
    {
        float4 bb = *reinterpret_cast<const float4*>(&b2[nd * 4]);
        unsigned long long bb01, bb23;
        PACK2P(bb01, bb.x, bb.y);
        PACK2P(bb23, bb.z, bb.w);
#pragma unroll
        for (int i = 0; i < 8; i++) { al[i] = bb01; ah[i] = bb23; }
    }
    GEMM_BODY();
#undef GEMM_BODY

    // relu + store
#pragma unroll
    for (int i = 0; i < 8; i++) {
        int node = node0 + ng + 32 * i;
        if (node < N_NODES) {
            float v0, v1, v2, v3;
            UNPACK2(v0, v1, al[i]); UNPACK2(v2, v3, ah[i]);
            float4 o = make_float4(fmaxf(v0, 0.f), fmaxf(v1, 0.f), fmaxf(v2, 0.f), fmaxf(v3, 0.f));
            *reinterpret_cast<float4*>(&out[node * DIM + nd * 4]) = o;
        }
    }
}

// ---------------------------------------------------------------------------
// Pool + head
// ---------------------------------------------------------------------------
__global__ void zero_pool_kernel(float* __restrict__ pool) {
    int i = blockIdx.x * blockDim.x + threadIdx.x;
    if (i < N_GRAPHS * DIM) pool[i] = 0.f;
}

#define POOL_NPB 256
__global__ void pool_kernel(const float* __restrict__ h,
                            const int* __restrict__ batch,
                            float* __restrict__ pool) {
    int d = threadIdx.x;
    int start = blockIdx.x * POOL_NPB;
    if (start >= N_NODES) return;
    int end = min(start + POOL_NPB, N_NODES);
    int g = batch[start];
    float acc = 0.f;
    for (int node = start; node < end; node++) {
        int bg = batch[node];
        if (bg != g) {
            atomicAdd(&pool[g * DIM + d], acc);
            acc = 0.f;
            g = bg;
        }
        acc += h[node * DIM + d];
    }
    atomicAdd(&pool[g * DIM + d], acc);
}

__global__ void head_kernel(const float* __restrict__ pool,
                            const float* __restrict__ w1, const float* __restrict__ b1v,
                            const float* __restrict__ w2, const float* __restrict__ b2v,
                            float* __restrict__ out) {
    __shared__ float sW[DIM][DIM];
    __shared__ float sH[N_GRAPHS][DIM];
    int tid = threadIdx.x;
    for (int i = tid; i < DIM * DIM; i += 128) sW[i >> 6][i & 63] = w1[i];
    __syncthreads();

    int g = tid;
    float row[DIM];
#pragma unroll
    for (int k = 0; k < DIM; k++) row[k] = pool[g * DIM + k];
#pragma unroll 4
    for (int j = 0; j < DIM; j++) {
        float acc = b1v[j];
#pragma unroll
        for (int k = 0; k < DIM; k++) acc += row[k] * sW[k][j];
        sH[g][j] = fmaxf(acc, 0.f);
    }
    __syncthreads();
#pragma unroll
    for (int o = 0; o < 10; o++) {
        float acc = b2v[o];
#pragma unroll
        for (int k = 0; k < DIM; k++) acc += sH[g][k] * w2[k * 10 + o];
        out[g * 10 + o] = acc;
    }
}

// ---------------------------------------------------------------------------
extern "C" void kernel_launch(void* const* d_in, const int* in_sizes, int n_in,
                              void* d_out, int out_size) {
    const float* x      = (const float*)d_in[0];
    const int*   ei     = (const int*)d_in[1];
    const int*   batch  = (const int*)d_in[2];
    const float* W1     = (const float*)d_in[3];
    const float* b1     = (const float*)d_in[4];
    const float* gamma  = (const float*)d_in[5];
    const float* beta   = (const float*)d_in[6];
    const float* rmean  = (const float*)d_in[7];
    const float* rvar   = (const float*)d_in[8];
    const float* W2     = (const float*)d_in[9];
    const float* b2     = (const float*)d_in[10];
    const float* lin1_w = (const float*)d_in[11];
    const float* lin1_b = (const float*)d_in[12];
    const float* lin2_w = (const float*)d_in[13];
    const float* lin2_b = (const float*)d_in[14];
    float* out = (float*)d_out;

    float *h0, *h1, *pool_buf;
    int *deg, *esrc_pad;
    cudaGetSymbolAddress((void**)&h0, g_h0);
    cudaGetSymbolAddress((void**)&h1, g_h1);
    cudaGetSymbolAddress((void**)&pool_buf, g_pool);
    cudaGetSymbolAddress((void**)&deg, g_deg);
    cudaGetSymbolAddress((void**)&esrc_pad, g_esrc_pad);

    // opt-in to >48KB dynamic smem (non-stream call; capture-safe, idempotent)
    static bool smem_cfg = false;
    if (!smem_cfg) {
        cudaFuncSetAttribute(layer_kernel,
                             cudaFuncAttributeMaxDynamicSharedMemorySize, SMEM_BYTES);
        smem_cfg = true;
    }

    const int eb = (N_EDGES + 255) / 256;
    const int nb = (N_NODES + 255) / 256;

    // --- Bucketed adjacency build ---
    fillb_kernel<<<eb, 256>>>(ei, deg, esrc_pad);

    // --- 5 fused GIN layers (ping-pong: never read+write same buffer) ---
    const int layer_blocks = (N_NODES + NODES_PER_CTA - 1) / NODES_PER_CTA;
    const float* cur = x;
    float* dst = h0;
    for (int l = 0; l < N_LAYERS; l++) {
        layer_kernel<<<layer_blocks, CTA_THREADS, SMEM_BYTES>>>(
            cur, dst, deg, esrc_pad,
            W1 + l * DIM * DIM, b1 + l * DIM,
            gamma + l * DIM, beta + l * DIM,
            rmean + l * DIM, rvar + l * DIM,
            W2 + l * DIM * DIM, b2 + l * DIM);
        cur = dst;
        dst = (dst == h0) ? h1 : h0;
    }
    const float* hfin = cur;

    // --- pool + head ---
    zero_pool_kernel<<<(N_GRAPHS * DIM + 255) / 256, 256>>>(pool_buf);
    pool_kernel<<<(N_NODES + POOL_NPB - 1) / POOL_NPB, 64>>>(hfin, batch, pool_buf);
    head_kernel<<<1, 128>>>(pool_buf, lin1_w, lin1_b, lin2_w, lin2_b, out);

    // --- trailing: reset deg for the NEXT invocation ---
    zero_deg_kernel<<<nb, 256>>>(deg);
}

// round 17
// speedup vs baseline: 1.0775x; 1.0775x over previous
#include <cuda_runtime.h>
#include <cuda_bf16.h>
#include <cstdint>

#define N_NODES 100000
#define N_EDGES 1600000
#define DIM 64
#define N_GRAPHS 128
#define N_LAYERS 5
#define BN_EPS 1e-5f
#define CAP 96   // per-node neighbor bucket capacity

#define NODES_PER_CTA 128
#define CTA_THREADS 512
#define NTILES ((N_NODES + NODES_PER_CTA - 1) / NODES_PER_CTA)   // 782
#define GRID 304   // 2 CTAs/SM x 152 SMs (GB300)
// dynamic smem: sW1 (16 KB) + sW2 (16 KB) + 2x sX (32 KB each) = 96 KB
#define SMEM_BYTES ((2 * DIM * DIM + 2 * NODES_PER_CTA * DIM) * 4)

// Scratch (allocation-free rule: __device__ globals)
__device__ float g_h0[N_NODES * DIM];
__device__ float g_h1[N_NODES * DIM];
__device__ float g_pool[N_GRAPHS * DIM];
__device__ int   g_deg[N_NODES];              // static zero-init; re-zeroed at END of each launch
__device__ int   g_esrc_pad[N_NODES * CAP];   // bucketed adjacency

// packed f32x2 helpers (FFMA2 only reachable via PTX)
#define PACK2(dst, x)  asm volatile("mov.b64 %0, {%1, %1};" : "=l"(dst) : "f"(x))
#define PACK2P(dst, lo, hi) asm volatile("mov.b64 %0, {%1, %2};" : "=l"(dst) : "f"(lo), "f"(hi))
#define UNPACK2(lo, hi, v) asm volatile("mov.b64 {%0, %1}, %2;" : "=f"(lo), "=f"(hi) : "l"(v))
#define FMA2(acc, xx, ww) asm volatile("fma.rn.f32x2 %0, %1, %2, %0;" : "+l"(acc) : "l"(xx), "l"(ww))

// one k-step of the register-tiled GEMM (R15-proven form)
#define KSTEP(koff, C) do { \
    unsigned long long w01, w23, x0, x1, x2, x3; \
    asm volatile("ld.shared.v2.u64 {%0, %1}, [%2];" \
                 : "=l"(w01), "=l"(w23) : "r"(wcol + (koff) * (DIM * 4))); \
    PACK2(x0, xa.C); PACK2(x1, xb.C); PACK2(x2, xc.C); PACK2(x3, xd.C); \
    FMA2(a0l, x0, w01); FMA2(a0h, x0, w23); \
    FMA2(a1l, x1, w01); FMA2(a1h, x1, w23); \
    FMA2(a2l, x2, w01); FMA2(a2h, x2, w23); \
    FMA2(a3l, x3, w01); FMA2(a3h, x3, w23); \
} while (0)

// ---------------------------------------------------------------------------
// Bucketed adjacency build (deg[] zero on entry; re-zeroed by trailing kernel)
// ---------------------------------------------------------------------------
__global__ void fillb_kernel(const int* __restrict__ ei,
                             int* __restrict__ deg,
                             int* __restrict__ esrc_pad) {
    int e = blockIdx.x * blockDim.x + threadIdx.x;
    if (e < N_EDGES) {
        int d = ei[N_EDGES + e];
        int c = atomicAdd(&deg[d], 1);
        if (c < CAP) esrc_pad[d * CAP + c] = ei[e];
    }
}

__global__ void zero_deg_kernel(int* __restrict__ deg) {
    int i = blockIdx.x * blockDim.x + threadIdx.x;
    if (i < N_NODES) deg[i] = 0;
}

// ---------------------------------------------------------------------------
// Gather one 128-node tile into sX (R15-proven body; 32 slots x 16 quads x 4)
// ---------------------------------------------------------------------------
__device__ __forceinline__ void gather_tile(
    const float* __restrict__ h, const int* __restrict__ deg,
    const int* __restrict__ esrc_pad, float (*sX)[DIM], int node0, int tid) {
    int g32 = tid >> 4;
    int l16 = tid & 15;
#pragma unroll
    for (int nb = 0; nb < 4; nb++) {
        int row = nb * 32 + g32;
        int node = node0 + row;
        float4 acc = make_float4(0.f, 0.f, 0.f, 0.f);
        if (node < N_NODES) {
            acc = *reinterpret_cast<const float4*>(&h[node * DIM + l16 * 4]);
            int dn = deg[node];
            if (dn > CAP) dn = CAP;
            const int* nb_base = &esrc_pad[node * CAP];
            int j = 0;
            for (; j + 7 < dn; j += 8) {
                int s0 = nb_base[j],     s1 = nb_base[j + 1], s2 = nb_base[j + 2], s3 = nb_base[j + 3];
                int s4 = nb_base[j + 4], s5 = nb_base[j + 5], s6 = nb_base[j + 6], s7 = nb_base[j + 7];
                float4 v0 = *reinterpret_cast<const float4*>(&h[s0 * DIM + l16 * 4]);
                float4 v1 = *reinterpret_cast<const float4*>(&h[s1 * DIM + l16 * 4]);
                float4 v2 = *reinterpret_cast<const float4*>(&h[s2 * DIM + l16 * 4]);
                float4 v3 = *reinterpret_cast<const float4*>(&h[s3 * DIM + l16 * 4]);
                float4 v4 = *reinterpret_cast<const float4*>(&h[s4 * DIM + l16 * 4]);
                float4 v5 = *reinterpret_cast<const float4*>(&h[s5 * DIM + l16 * 4]);
                float4 v6 = *reinterpret_cast<const float4*>(&h[s6 * DIM + l16 * 4]);
                float4 v7 = *reinterpret_cast<const float4*>(&h[s7 * DIM + l16 * 4]);
                acc.x += ((v0.x + v1.x) + (v2.x + v3.x)) + ((v4.x + v5.x) + (v6.x + v7.x));
                acc.y += ((v0.y + v1.y) + (v2.y + v3.y)) + ((v4.y + v5.y) + (v6.y + v7.y));
                acc.z += ((v0.z + v1.z) + (v2.z + v3.z)) + ((v4.z + v5.z) + (v6.z + v7.z));
                acc.w += ((v0.w + v1.w) + (v2.w + v3.w)) + ((v4.w + v5.w) + (v6.w + v7.w));
            }
            for (; j + 3 < dn; j += 4) {
                int s0 = nb_base[j], s1 = nb_base[j + 1], s2 = nb_base[j + 2], s3 = nb_base[j + 3];
                float4 v0 = *reinterpret_cast<const float4*>(&h[s0 * DIM + l16 * 4]);
                float4 v1 = *reinterpret_cast<const float4*>(&h[s1 * DIM + l16 * 4]);
                float4 v2 = *reinterpret_cast<const float4*>(&h[s2 * DIM + l16 * 4]);
                float4 v3 = *reinterpret_cast<const float4*>(&h[s3 * DIM + l16 * 4]);
                acc.x += (v0.x + v1.x) + (v2.x + v3.x);
                acc.y += (v0.y + v1.y) + (v2.y + v3.y);
                acc.z += (v0.z + v1.z) + (v2.z + v3.z);
                acc.w += (v0.w + v1.w) + (v2.w + v3.w);
            }
            for (; j < dn; j++) {
                float4 v = *reinterpret_cast<const float4*>(&h[nb_base[j] * DIM + l16 * 4]);
                acc.x += v.x; acc.y += v.y; acc.z += v.z; acc.w += v.w;
            }
        }
        *reinterpret_cast<float4*>(&sX[row][l16 * 4]) = acc;
    }
}

// ---------------------------------------------------------------------------
// Pipelined fused layer: persistent-ish CTAs (grid=304) grid-stride over
// 128-node tiles with double-buffered sX. Per iteration a warp issues
// gather(t+1) then GEMM(t) with NO barrier between -> warps spread across
// memory and compute instead of aligning at a phase boundary.
// ---------------------------------------------------------------------------
__global__ void __launch_bounds__(CTA_THREADS, 2) layer_kernel(
    const float* __restrict__ h, float* __restrict__ out,
    const int* __restrict__ deg, const int* __restrict__ esrc_pad,
    const float* __restrict__ W1, const float* __restrict__ b1,
    const float* __restrict__ gamma, const float* __restrict__ beta,
    const float* __restrict__ rmean, const float* __restrict__ rvar,
    const float* __restrict__ W2, const float* __restrict__ b2) {
    extern __shared__ float smem[];
    float (*sW1)[DIM] = reinterpret_cast<float(*)[DIM]>(smem);
    float (*sW2)[DIM] = reinterpret_cast<float(*)[DIM]>(smem + DIM * DIM);
    float (*sX0)[DIM] = reinterpret_cast<float(*)[DIM]>(smem + 2 * DIM * DIM);
    float (*sX1)[DIM] = reinterpret_cast<float(*)[DIM]>(smem + 2 * DIM * DIM + NODES_PER_CTA * DIM);

    int tid = threadIdx.x;

    // load both weights once per CTA
    for (int i = tid; i < DIM * DIM; i += CTA_THREADS) {
        sW1[i >> 6][i & 63] = W1[i];
        sW2[i >> 6][i & 63] = W2[i];
    }

    int nd = tid & 15;   // dim group
    int ng = tid >> 4;   // node slot (0..31)
    uint32_t sw1_base = (uint32_t)__cvta_generic_to_shared(sW1) + nd * 16;
    uint32_t sw2_base = (uint32_t)__cvta_generic_to_shared(sW2) + nd * 16;

    // prologue: gather first tile
    int t = blockIdx.x;
    gather_tile(h, deg, esrc_pad, sX0, t * NODES_PER_CTA, tid);
    __syncthreads();

    int p = 0;
    while (true) {
        float (*sXc)[DIM] = p ? sX1 : sX0;
        float (*sXn)[DIM] = p ? sX0 : sX1;
        int tn = t + GRID;

        // overlap region: gather next tile (mem) ... GEMM1 current (compute)
        if (tn < NTILES)
            gather_tile(h, deg, esrc_pad, sXn, tn * NODES_PER_CTA, tid);

        // ---- GEMM 1 from sXc, sW1 ----
        unsigned long long a0l = 0, a0h = 0, a1l = 0, a1h = 0;
        unsigned long long a2l = 0, a2h = 0, a3l = 0, a3h = 0;
        {
            uint32_t wcol = sw1_base;
#pragma unroll 4
            for (int k4 = 0; k4 < DIM; k4 += 4) {
                float4 xa = *reinterpret_cast<const float4*>(&sXc[ng][k4]);
                float4 xb = *reinterpret_cast<const float4*>(&sXc[ng + 32][k4]);
                float4 xc = *reinterpret_cast<const float4*>(&sXc[ng + 64][k4]);
                float4 xd = *reinterpret_cast<const float4*>(&sXc[ng + 96][k4]);
                KSTEP(k4 + 0, x);
                KSTEP(k4 + 1, y);
                KSTEP(k4 + 2, z);
                KSTEP(k4 + 3, w);
            }
        }
        __syncthreads();  // GEMM1 reads of sXc done

        // ---- BN + relu -> sXc ----
        {
            float bnA[4], bnB[4];
#pragma unroll
            for (int j = 0; j < 4; j++) {
                int d = nd * 4 + j;
                float s = gamma[d] * rsqrtf(rvar[d] + BN_EPS);
                bnA[j] = s;
                bnB[j] = (b1[d] - rmean[d]) * s + beta[d];
            }
            float v0, v1, v2, v3;
            UNPACK2(v0, v1, a0l); UNPACK2(v2, v3, a0h);
            sXc[ng][nd * 4 + 0] = fmaxf(v0 * bnA[0] + bnB[0], 0.f);
            sXc[ng][nd * 4 + 1] = fmaxf(v1 * bnA[1] + bnB[1], 0.f);
            sXc[ng][nd * 4 + 2] = fmaxf(v2 * bnA[2] + bnB[2], 0.f);
            sXc[ng][nd * 4 + 3] = fmaxf(v3 * bnA[3] + bnB[3], 0.f);
            UNPACK2(v0, v1, a1l); UNPACK2(v2, v3, a1h);
            sXc[ng + 32][nd * 4 + 0] = fmaxf(v0 * bnA[0] + bnB[0], 0.f);
            sXc[ng + 32][nd * 4 + 1] = fmaxf(v1 * bnA[1] + bnB[1], 0.f);
            sXc[ng + 32][nd * 4 + 2] = fmaxf(v2 * bnA[2] + bnB[2], 0.f);
            sXc[ng + 32][nd * 4 + 3] = fmaxf(v3 * bnA[3] + bnB[3], 0.f);
            UNPACK2(v0, v1, a2l); UNPACK2(v2, v3, a2h);
            sXc[ng + 64][nd * 4 + 0] = fmaxf(v0 * bnA[0] + bnB[0], 0.f);
            sXc[ng + 64][nd * 4 + 1] = fmaxf(v1 * bnA[1] + bnB[1], 0.f);
            sXc[ng + 64][nd * 4 + 2] = fmaxf(v2 * bnA[2] + bnB[2], 0.f);
            sXc[ng + 64][nd * 4 + 3] = fmaxf(v3 * bnA[3] + bnB[3], 0.f);
            UNPACK2(v0, v1, a3l); UNPACK2(v2, v3, a3h);
            sXc[ng + 96][nd * 4 + 0] = fmaxf(v0 * bnA[0] + bnB[0], 0.f);
            sXc[ng + 96][nd * 4 + 1] = fmaxf(v1 * bnA[1] + bnB[1], 0.f);
            sXc[ng + 96][nd * 4 + 2] = fmaxf(v2 * bnA[2] + bnB[2], 0.f);
            sXc[ng + 96][nd * 4 + 3] = fmaxf(v3 * bnA[3] + bnB[3], 0.f);
        }
        __syncthreads();  // BN writes to sXc done

        // ---- GEMM 2 from sXc, sW2, pre-seeded with b2; relu + store ----
        {
            float4 bb = *reinterpret_cast<const float4*>(&b2[nd * 4]);
            unsigned long long bb01, bb23;
            PACK2P(bb01, bb.x, bb.y);
            PACK2P(bb23, bb.z, bb.w);
            a0l = bb01; a0h = bb23;
            a1l = bb01; a1h = bb23;
            a2l = bb01; a2h = bb23;
            a3l = bb01; a3h = bb23;
            uint32_t wcol = sw2_base;
#pragma unroll 4
            for (int k4 = 0; k4 < DIM; k4 += 4) {
                float4 xa = *reinterpret_cast<const float4*>(&sXc[ng][k4]);
                float4 xb = *reinterpret_cast<const float4*>(&sXc[ng + 32][k4]);
                float4 xc = *reinterpret_cast<const float4*>(&sXc[ng + 64][k4]);
                float4 xd = *reinterpret_cast<const float4*>(&sXc[ng + 96][k4]);
                KSTEP(k4 + 0, x);
                KSTEP(k4 + 1, y);
                KSTEP(k4 + 2, z);
                KSTEP(k4 + 3, w);
            }
        }
        {
            int node0t = t * NODES_PER_CTA;
            float v0, v1, v2, v3;
            int node;
            node = node0t + ng;
            if (node < N_NODES) {
                UNPACK2(v0, v1, a0l); UNPACK2(v2, v3, a0h);
                float4 o = make_float4(fmaxf(v0, 0.f), fmaxf(v1, 0.f), fmaxf(v2, 0.f), fmaxf(v3, 0.f));
                *reinterpret_cast<float4*>(&out[node * DIM + nd * 4]) = o;
            }
            node = node0t + ng + 32;
            if (node < N_NODES) {
                UNPACK2(v0, v1, a1l); UNPACK2(v2, v3, a1h);
                float4 o = make_float4(fmaxf(v0, 0.f), fmaxf(v1, 0.f), fmaxf(v2, 0.f), fmaxf(v3, 0.f));
                *reinterpret_cast<float4*>(&out[node * DIM + nd * 4]) = o;
            }
            node = node0t + ng + 64;
            if (node < N_NODES) {
                UNPACK2(v0, v1, a2l); UNPACK2(v2, v3, a2h);
                float4 o = make_float4(fmaxf(v0, 0.f), fmaxf(v1, 0.f), fmaxf(v2, 0.f), fmaxf(v3, 0.f));
                *reinterpret_cast<float4*>(&out[node * DIM + nd * 4]) = o;
            }
            node = node0t + ng + 96;
            if (node < N_NODES) {
                UNPACK2(v0, v1, a3l); UNPACK2(v2, v3, a3h);
                float4 o = make_float4(fmaxf(v0, 0.f), fmaxf(v1, 0.f), fmaxf(v2, 0.f), fmaxf(v3, 0.f));
                *reinterpret_cast<float4*>(&out[node * DIM + nd * 4]) = o;
            }
        }

        if (tn >= NTILES) break;   // uniform across CTA
        __syncthreads();           // GEMM2 reads of sXc done before reuse as next sXn
        t = tn;
        p ^= 1;
    }
}

// ---------------------------------------------------------------------------
// Pool + head
// ---------------------------------------------------------------------------
__global__ void zero_pool_kernel(float* __restrict__ pool) {
    int i = blockIdx.x * blockDim.x + threadIdx.x;
    if (i < N_GRAPHS * DIM) pool[i] = 0.f;
}

#define POOL_NPB 256
__global__ void pool_kernel(const float* __restrict__ h,
                            const int* __restrict__ batch,
                            float* __restrict__ pool) {
    int d = threadIdx.x;
    int start = blockIdx.x * POOL_NPB;
    if (start >= N_NODES) return;
    int end = min(start + POOL_NPB, N_NODES);
    int g = batch[start];
    float acc = 0.f;
    for (int node = start; node < end; node++) {
        int bg = batch[node];
        if (bg != g) {
            atomicAdd(&pool[g * DIM + d], acc);
            acc = 0.f;
            g = bg;
        }
        acc += h[node * DIM + d];
    }
    atomicAdd(&pool[g * DIM + d], acc);
}

__global__ void head_kernel(const float* __restrict__ pool,
                            const float* __restrict__ w1, const float* __restrict__ b1v,
                            const float* __restrict__ w2, const float* __restrict__ b2v,
                            float* __restrict__ out) {
    __shared__ float sW[DIM][DIM];
    __shared__ float sH[N_GRAPHS][DIM];
    int tid = threadIdx.x;
    for (int i = tid; i < DIM * DIM; i += 128) sW[i >> 6][i & 63] = w1[i];
    __syncthreads();

    int g = tid;
    float row[DIM];
#pragma unroll
    for (int k = 0; k < DIM; k++) row[k] = pool[g * DIM + k];
#pragma unroll 4
    for (int j = 0; j < DIM; j++) {
        float acc = b1v[j];
#pragma unroll
        for (int k = 0; k < DIM; k++) acc += row[k] * sW[k][j];
        sH[g][j] = fmaxf(acc, 0.f);
    }
    __syncthreads();
#pragma unroll
    for (int o = 0; o < 10; o++) {
        float acc = b2v[o];
#pragma unroll
        for (int k = 0; k < DIM; k++) acc += sH[g][k] * w2[k * 10 + o];
        out[g * 10 + o] = acc;
    }
}

// ---------------------------------------------------------------------------
extern "C" void kernel_launch(void* const* d_in, const int* in_sizes, int n_in,
                              void* d_out, int out_size) {
    const float* x      = (const float*)d_in[0];
    const int*   ei     = (const int*)d_in[1];
    const int*   batch  = (const int*)d_in[2];
    const float* W1     = (const float*)d_in[3];
    const float* b1     = (const float*)d_in[4];
    const float* gamma  = (const float*)d_in[5];
    const float* beta   = (const float*)d_in[6];
    const float* rmean  = (const float*)d_in[7];
    const float* rvar   = (const float*)d_in[8];
    const float* W2     = (const float*)d_in[9];
    const float* b2     = (const float*)d_in[10];
    const float* lin1_w = (const float*)d_in[11];
    const float* lin1_b = (const float*)d_in[12];
    const float* lin2_w = (const float*)d_in[13];
    const float* lin2_b = (const float*)d_in[14];
    float* out = (float*)d_out;

    float *h0, *h1, *pool_buf;
    int *deg, *esrc_pad;
    cudaGetSymbolAddress((void**)&h0, g_h0);
    cudaGetSymbolAddress((void**)&h1, g_h1);
    cudaGetSymbolAddress((void**)&pool_buf, g_pool);
    cudaGetSymbolAddress((void**)&deg, g_deg);
    cudaGetSymbolAddress((void**)&esrc_pad, g_esrc_pad);

    // opt-in to >48KB dynamic smem (non-stream call; capture-safe, idempotent)
    static bool smem_cfg = false;
    if (!smem_cfg) {
        cudaFuncSetAttribute(layer_kernel,
                             cudaFuncAttributeMaxDynamicSharedMemorySize, SMEM_BYTES);
        smem_cfg = true;
    }

    const int eb = (N_EDGES + 255) / 256;
    const int nb = (N_NODES + 255) / 256;

    // --- Bucketed adjacency build ---
    fillb_kernel<<<eb, 256>>>(ei, deg, esrc_pad);

    // --- 5 pipelined GIN layers (ping-pong: never read+write same buffer) ---
    const float* cur = x;
    float* dst = h0;
    for (int l = 0; l < N_LAYERS; l++) {
        layer_kernel<<<GRID, CTA_THREADS, SMEM_BYTES>>>(
            cur, dst, deg, esrc_pad,
            W1 + l * DIM * DIM, b1 + l * DIM,
            gamma + l * DIM, beta + l * DIM,
            rmean + l * DIM, rvar + l * DIM,
            W2 + l * DIM * DIM, b2 + l * DIM);
        cur = dst;
        dst = (dst == h0) ? h1 : h0;
    }
    const float* hfin = cur;

    // --- pool + head ---
    zero_pool_kernel<<<(N_GRAPHS * DIM + 255) / 256, 256>>>(pool_buf);
    pool_kernel<<<(N_NODES + POOL_NPB - 1) / POOL_NPB, 64>>>(hfin, batch, pool_buf);
    head_kernel<<<1, 128>>>(pool_buf, lin1_w, lin1_b, lin2_w, lin2_b, out);

    // --- trailing: reset deg for the NEXT invocation ---
    zero_deg_kernel<<<nb, 256>>>(deg);
}